// round 13
// baseline (speedup 1.0000x reference)
#include <cuda_runtime.h>
#include <cuda_bf16.h>
#include <cstdint>

// ============================================================================
// AttentionWithRoPE — round 13: cp.async double-buffered K/V loads in the
// attention kernel (one isolated change vs round 12's 2104us kernel).
//   B=2, N=2048, D=2048, H=16, Dh=128
// ============================================================================

#define BATCH   2
#define SEQ     2048
#define DMODEL  2048
#define HEADS   16
#define DH      128
#define ROWS    (BATCH * SEQ)          // 4096
#define KSPLIT  (3 * DMODEL)           // 6144

// ---- scratch (static __device__, no allocations; 16B-aligned) ----
__device__ __align__(16) float g_q[ROWS * DMODEL];
__device__ __align__(16) float g_k[ROWS * DMODEL];
__device__ __align__(16) float g_v[ROWS * DMODEL];
__device__ __align__(16) __nv_bfloat16 g_a  [ROWS * KSPLIT];
__device__ __align__(16) __nv_bfloat16 g_wq [KSPLIT * DMODEL];
__device__ __align__(16) __nv_bfloat16 g_wk [KSPLIT * DMODEL];
__device__ __align__(16) __nv_bfloat16 g_wv [KSPLIT * DMODEL];
__device__ __align__(16) __nv_bfloat16 g_wo [KSPLIT * DMODEL];

// ============================================================================
// common MMA / ldmatrix helpers
// ============================================================================
__device__ __forceinline__ void cp16(uint32_t smem_addr, const void* gptr) {
    asm volatile("cp.async.cg.shared.global [%0], [%1], 16;"
                 :: "r"(smem_addr), "l"(gptr));
}
__device__ __forceinline__ void cp_commit() {
    asm volatile("cp.async.commit_group;");
}
template <int Nwait>
__device__ __forceinline__ void cp_wait() {
    asm volatile("cp.async.wait_group %0;" :: "n"(Nwait));
}
__device__ __forceinline__ void ldsm_x4(uint32_t& r0, uint32_t& r1,
                                        uint32_t& r2, uint32_t& r3,
                                        uint32_t addr) {
    asm volatile("ldmatrix.sync.aligned.m8n8.x4.shared.b16 {%0,%1,%2,%3}, [%4];"
                 : "=r"(r0), "=r"(r1), "=r"(r2), "=r"(r3) : "r"(addr));
}
__device__ __forceinline__ void ldsm_x4_t(uint32_t& r0, uint32_t& r1,
                                          uint32_t& r2, uint32_t& r3,
                                          uint32_t addr) {
    asm volatile("ldmatrix.sync.aligned.m8n8.x4.trans.shared.b16 {%0,%1,%2,%3}, [%4];"
                 : "=r"(r0), "=r"(r1), "=r"(r2), "=r"(r3) : "r"(addr));
}
__device__ __forceinline__ void mma16816(float& c0, float& c1, float& c2, float& c3,
                                         uint32_t a0, uint32_t a1, uint32_t a2,
                                         uint32_t a3, uint32_t b0, uint32_t b1) {
    asm volatile(
        "mma.sync.aligned.m16n8k16.row.col.f32.bf16.bf16.f32 "
        "{%0,%1,%2,%3}, {%4,%5,%6,%7}, {%8,%9}, {%0,%1,%2,%3};"
        : "+f"(c0), "+f"(c1), "+f"(c2), "+f"(c3)
        : "r"(a0), "r"(a1), "r"(a2), "r"(a3), "r"(b0), "r"(b1));
}
__device__ __forceinline__ uint32_t pack_bf16x2(__nv_bfloat16 lo, __nv_bfloat16 hi) {
    __nv_bfloat162 p = __halves2bfloat162(lo, hi);
    return *reinterpret_cast<uint32_t*>(&p);
}

// ============================================================================
// hi/lo split kernels — SCALAR (verified)
// ============================================================================
__global__ __launch_bounds__(256)
void split_a_kernel(const float* __restrict__ X, __nv_bfloat16* __restrict__ A) {
    int i = blockIdx.x * blockDim.x + threadIdx.x;
    if (i >= ROWS * DMODEL) return;
    int r = i / DMODEL, c = i % DMODEL;
    float x = X[i];
    __nv_bfloat16 hi = __float2bfloat16(x);
    __nv_bfloat16 lo = __float2bfloat16(x - __bfloat162float(hi));
    __nv_bfloat16* row = A + (size_t)r * KSPLIT;
    row[c]              = hi;
    row[DMODEL + c]     = lo;
    row[2 * DMODEL + c] = hi;
}
__global__ __launch_bounds__(256)
void split_b_kernel(const float* __restrict__ W, __nv_bfloat16* __restrict__ Bo) {
    int i = blockIdx.x * blockDim.x + threadIdx.x;
    if (i >= DMODEL * DMODEL) return;
    float w = W[i];
    __nv_bfloat16 hi = __float2bfloat16(w);
    __nv_bfloat16 lo = __float2bfloat16(w - __bfloat162float(hi));
    Bo[i]                                 = hi;
    Bo[(size_t)DMODEL * DMODEL + i]       = hi;
    Bo[(size_t)2 * DMODEL * DMODEL + i]   = lo;
}

// ============================================================================
// bf16 tensor-core GEMM body: BM=BN=128, BK=64, 3-stage single-sync (round 12)
// ============================================================================
#define GBM 128
#define GBN 128
#define GBK 64
#define GSTAGES 3
#define APITCH 72
#define BPITCH 136
#define A_STAGE_ELEMS (GBM * APITCH)   // 9216
#define B_STAGE_ELEMS (GBK * BPITCH)   // 8704
#define GEMM_SMEM_BYTES (GSTAGES * (A_STAGE_ELEMS + B_STAGE_ELEMS) * 2)  // 107520

__device__ __forceinline__ void gemm_body(const __nv_bfloat16* __restrict__ A,
                                          const __nv_bfloat16* __restrict__ B,
                                          float* __restrict__ C,
                                          int M, int N, int K,
                                          const float* __restrict__ bias) {
    extern __shared__ __nv_bfloat16 sm[];
    __nv_bfloat16* sA = sm;
    __nv_bfloat16* sB = sm + GSTAGES * A_STAGE_ELEMS;

    const int tid  = threadIdx.x;
    const int warp = tid >> 5;
    const int lane = tid & 31;
    const int wm = warp >> 2;
    const int wn = warp & 3;
    const int bx = blockIdx.x;
    const int by = blockIdx.y;

    const int at_row   = tid >> 3;
    const int at_chunk = (tid & 7) << 3;
    const int bt_row   = tid >> 4;
    const int bt_chunk = (tid & 15) << 3;

    const __nv_bfloat16* Ag = A + (size_t)(by * GBM + at_row) * K + at_chunk;
    const __nv_bfloat16* Bg = B + (size_t)bt_row * N + bx * GBN + bt_chunk;

    uint32_t sA_u32 = (uint32_t)__cvta_generic_to_shared(sA);
    uint32_t sB_u32 = (uint32_t)__cvta_generic_to_shared(sB);

    auto load_tile = [&](int stage, int k0) {
        uint32_t a_dst = sA_u32 + (stage * A_STAGE_ELEMS + at_row * APITCH + at_chunk) * 2;
#pragma unroll
        for (int b = 0; b < 4; b++)
            cp16(a_dst + b * 32 * APITCH * 2, Ag + (size_t)(32 * b) * K + k0);
        uint32_t b_dst = sB_u32 + (stage * B_STAGE_ELEMS + bt_row * BPITCH + bt_chunk) * 2;
#pragma unroll
        for (int b = 0; b < 4; b++)
            cp16(b_dst + b * 16 * BPITCH * 2, Bg + (size_t)(k0 + 16 * b) * N);
    };

    float acc[4][4][4];
#pragma unroll
    for (int i = 0; i < 4; i++)
#pragma unroll
        for (int j = 0; j < 4; j++)
#pragma unroll
            for (int r = 0; r < 4; r++) acc[i][j][r] = 0.0f;

    const int KT = K / GBK;   // 96

    load_tile(0, 0);        cp_commit();
    load_tile(1, GBK);      cp_commit();

    const int a_lrow = (lane & 15);
    const int a_lcol = (lane >> 4) << 3;

    int st = 0, wst = 2;
    for (int kt = 0; kt < KT; kt++) {
        cp_wait<1>();
        __syncthreads();

        if (kt + 2 < KT) load_tile(wst, (kt + 2) * GBK);
        cp_commit();

        uint32_t aBase = sA_u32 + (st * A_STAGE_ELEMS) * 2;
        uint32_t bBase = sB_u32 + (st * B_STAGE_ELEMS) * 2;

#pragma unroll
        for (int ks = 0; ks < 4; ks++) {
            uint32_t a[4][4];
#pragma unroll
            for (int i = 0; i < 4; i++) {
                int row = wm * 64 + i * 16 + a_lrow;
                int col = ks * 16 + a_lcol;
                ldsm_x4(a[i][0], a[i][1], a[i][2], a[i][3],
                        aBase + (row * APITCH + col) * 2);
            }
            uint32_t b[4][2];
#pragma unroll
            for (int j2 = 0; j2 < 2; j2++) {
                int row = ks * 16 + a_lrow;
                int col = wn * 32 + j2 * 16 + a_lcol;
                uint32_t r0, r1, r2, r3;
                ldsm_x4_t(r0, r1, r2, r3, bBase + (row * BPITCH + col) * 2);
                b[2 * j2][0] = r0; b[2 * j2][1] = r1;
                b[2 * j2 + 1][0] = r2; b[2 * j2 + 1][1] = r3;
            }
#pragma unroll
            for (int i = 0; i < 4; i++)
#pragma unroll
                for (int j = 0; j < 4; j++)
                    mma16816(acc[i][j][0], acc[i][j][1], acc[i][j][2], acc[i][j][3],
                             a[i][0], a[i][1], a[i][2], a[i][3],
                             b[j][0], b[j][1]);
        }

        if (++st == GSTAGES) st = 0;
        if (++wst == GSTAGES) wst = 0;
    }

    const int row_base = by * GBM + wm * 64 + (lane >> 2);
    const int col_base = bx * GBN + wn * 32 + (lane & 3) * 2;
#pragma unroll
    for (int i = 0; i < 4; i++) {
#pragma unroll
        for (int j = 0; j < 4; j++) {
            int c = col_base + j * 8;
            float b0 = bias ? bias[c]     : 0.0f;
            float b1 = bias ? bias[c + 1] : 0.0f;
            float* p0 = C + (size_t)(row_base + i * 16) * N + c;
            float* p1 = C + (size_t)(row_base + i * 16 + 8) * N + c;
            p0[0] = acc[i][j][0] + b0; p0[1] = acc[i][j][1] + b1;
            p1[0] = acc[i][j][2] + b0; p1[1] = acc[i][j][3] + b1;
        }
    }
}

__global__ __launch_bounds__(256, 2)
void gemm_bf16_kernel(const __nv_bfloat16* __restrict__ A,
                      const __nv_bfloat16* __restrict__ B,
                      float* __restrict__ C, int M, int N, int K,
                      const float* __restrict__ bias) {
    gemm_body(A, B, C, M, N, K, bias);
}

__global__ __launch_bounds__(256, 2)
void gemm_qkv_kernel(const __nv_bfloat16* __restrict__ A,
                     const __nv_bfloat16* __restrict__ Bq,
                     const __nv_bfloat16* __restrict__ Bk,
                     const __nv_bfloat16* __restrict__ Bv,
                     float* __restrict__ Cq,
                     float* __restrict__ Ck,
                     float* __restrict__ Cv,
                     int M, int N, int K) {
    const __nv_bfloat16* B = (blockIdx.z == 0) ? Bq : (blockIdx.z == 1) ? Bk : Bv;
    float*               C = (blockIdx.z == 0) ? Cq : (blockIdx.z == 1) ? Ck : Cv;
    gemm_body(A, B, C, M, N, K, nullptr);
}

// ============================================================================
// RoPE
// ============================================================================
__global__ __launch_bounds__(256)
void rope_kernel(float* __restrict__ X, const float* __restrict__ rope,
                 float scale) {
    int i = blockIdx.x * blockDim.x + threadIdx.x;
    int p  = i & 63;
    int h  = (i >> 6) & 15;
    int bn = i >> 10;
    float rr = rope[bn * DH + 2 * p];
    float ri = rope[bn * DH + 2 * p + 1];
    float* base = X + (size_t)bn * DMODEL + h * DH + 2 * p;
    float xr = base[0] * scale;
    float xi = base[1] * scale;
    base[0] = xr * rr - xi * ri;
    base[1] = xr * ri + xi * rr;
}

// ============================================================================
// MMA flash attention, hi/lo split, NOW with cp.async-staged K/V loads.
// smem: Qhi/Qlo [128][136], Khi/Klo/Vhi/Vlo [64][136] bf16, + fp32 staging
// for next K and V tiles (64x128 floats each = 64KB).
// ============================================================================
#define AQT   128
#define AKT   64
#define APIT  136
#define AQ_ELEMS  (AQT * APIT)
#define AKV_ELEMS (AKT * APIT)
#define ATT_BF16_ELEMS (2 * AQ_ELEMS + 4 * AKV_ELEMS)          // 69632
#define ATT_STAGE_FLOATS (AKT * DH)                            // 8192 per tensor
#define ATT3_SMEM_BYTES (ATT_BF16_ELEMS * 2 + 2 * ATT_STAGE_FLOATS * 4)  // 204800

__device__ __forceinline__ void split_store4(__nv_bfloat16* hiP,
                                             __nv_bfloat16* loP, float4 v) {
    __nv_bfloat16 h0 = __float2bfloat16(v.x);
    __nv_bfloat16 h1 = __float2bfloat16(v.y);
    __nv_bfloat16 h2 = __float2bfloat16(v.z);
    __nv_bfloat16 h3 = __float2bfloat16(v.w);
    __nv_bfloat16 l0 = __float2bfloat16(v.x - __bfloat162float(h0));
    __nv_bfloat16 l1 = __float2bfloat16(v.y - __bfloat162float(h1));
    __nv_bfloat16 l2 = __float2bfloat16(v.z - __bfloat162float(h2));
    __nv_bfloat16 l3 = __float2bfloat16(v.w - __bfloat162float(h3));
    *(__nv_bfloat162*)(hiP)     = __halves2bfloat162(h0, h1);
    *(__nv_bfloat162*)(hiP + 2) = __halves2bfloat162(h2, h3);
    *(__nv_bfloat162*)(loP)     = __halves2bfloat162(l0, l1);
    *(__nv_bfloat162*)(loP + 2) = __halves2bfloat162(l2, l3);
}

__device__ __forceinline__ void store_split2(__nv_bfloat16* row, int c,
                                             float v0, float v1) {
    __nv_bfloat16 h0 = __float2bfloat16(v0);
    __nv_bfloat16 h1 = __float2bfloat16(v1);
    __nv_bfloat16 l0 = __float2bfloat16(v0 - __bfloat162float(h0));
    __nv_bfloat16 l1 = __float2bfloat16(v1 - __bfloat162float(h1));
    __nv_bfloat162 hp = __halves2bfloat162(h0, h1);
    *(__nv_bfloat162*)(row + c)              = hp;
    *(__nv_bfloat162*)(row + DMODEL + c)     = __halves2bfloat162(l0, l1);
    *(__nv_bfloat162*)(row + 2 * DMODEL + c) = hp;
}

__global__ __launch_bounds__(256, 1)
void attn_mma_kernel(const float* __restrict__ Q, const float* __restrict__ K,
                     const float* __restrict__ V,
                     __nv_bfloat16* __restrict__ Oa) {
    extern __shared__ __nv_bfloat16 smb[];
    __nv_bfloat16* Qhi = smb;
    __nv_bfloat16* Qlo = smb + AQ_ELEMS;
    __nv_bfloat16* Khi = smb + 2 * AQ_ELEMS;
    __nv_bfloat16* Klo = Khi + AKV_ELEMS;
    __nv_bfloat16* Vhi = Klo + AKV_ELEMS;
    __nv_bfloat16* Vlo = Vhi + AKV_ELEMS;
    float* stK = (float*)(smb + ATT_BF16_ELEMS);           // [64*128] packed
    float* stV = stK + ATT_STAGE_FLOATS;

    const int tid  = threadIdx.x;
    const int warp = tid >> 5;
    const int lane = tid & 31;
    const int qt = blockIdx.x;
    const int bh = blockIdx.y;
    const int b  = bh >> 4;
    const int h  = bh & 15;

    const float* Qg = Q + ((size_t)b * SEQ + qt * AQT) * DMODEL + h * DH;
    const float* Kg = K + ((size_t)b * SEQ) * DMODEL + h * DH;
    const float* Vg = V + ((size_t)b * SEQ) * DMODEL + h * DH;
    __nv_bfloat16* Og = Oa + ((size_t)b * SEQ + qt * AQT) * KSPLIT + h * DH;

    uint32_t stK_u32 = (uint32_t)__cvta_generic_to_shared(stK);
    uint32_t stV_u32 = (uint32_t)__cvta_generic_to_shared(stV);

    // async loader for K/V tile kt into staging (packed 64x128 floats)
    auto load_kv_async = [&](int kt) {
        const float* Ks = Kg + (size_t)(kt * AKT) * DMODEL;
        const float* Vs = Vg + (size_t)(kt * AKT) * DMODEL;
#pragma unroll
        for (int it = 0; it < 8; it++) {
            int idx = tid + it * 256;          // 0..2047
            int r = idx >> 5, c4 = (idx & 31) << 2;
            cp16(stK_u32 + idx * 16, Ks + (size_t)r * DMODEL + c4);
            cp16(stV_u32 + idx * 16, Vs + (size_t)r * DMODEL + c4);
        }
    };

    // ---- load + split Q (synchronous, once) ----
#pragma unroll
    for (int it = 0; it < 16; it++) {
        int idx = tid + it * 256;
        int r = idx >> 5, c4 = (idx & 31) << 2;
        float4 v = *(const float4*)(Qg + (size_t)r * DMODEL + c4);
        split_store4(Qhi + r * APIT + c4, Qlo + r * APIT + c4, v);
    }

    // prologue: stage tile 0
    load_kv_async(0);
    cp_commit();

    uint32_t uQhi = (uint32_t)__cvta_generic_to_shared(Qhi);
    uint32_t uQlo = (uint32_t)__cvta_generic_to_shared(Qlo);
    uint32_t uKhi = (uint32_t)__cvta_generic_to_shared(Khi);
    uint32_t uKlo = (uint32_t)__cvta_generic_to_shared(Klo);
    uint32_t uVhi = (uint32_t)__cvta_generic_to_shared(Vhi);
    uint32_t uVlo = (uint32_t)__cvta_generic_to_shared(Vlo);

    const float sscale = 0.08838834764831845f;

    float m0 = -1e30f, m1 = -1e30f, l0 = 0.0f, l1 = 0.0f;
    float oacc[16][4];
#pragma unroll
    for (int nt = 0; nt < 16; nt++)
#pragma unroll
        for (int e = 0; e < 4; e++) oacc[nt][e] = 0.0f;

    const int rowA = lane & 15;
    const int colA = (lane >> 4) << 3;
    const int rowK = (lane & 7) + ((lane >> 4) << 3);
    const int colK = ((lane >> 3) & 1) << 3;
    const int rowV = lane & 15;
    const int colV = (lane >> 4) << 3;

    const uint32_t qhiBase = uQhi + ((warp * 16 + rowA) * APIT) * 2;
    const uint32_t qloBase = uQlo + ((warp * 16 + rowA) * APIT) * 2;

    const int NT = SEQ / AKT;
    for (int kt = 0; kt < NT; kt++) {
        cp_wait<0>();
        __syncthreads();   // staged tile kt visible; prior compute done w/ bf16 bufs

        // ---- convert stage -> bf16 hi/lo buffers ----
#pragma unroll
        for (int it = 0; it < 8; it++) {
            int idx = tid + it * 256;
            int r = idx >> 5, c4 = (idx & 31) << 2;
            float4 kv = *(const float4*)(stK + idx * 4);
            split_store4(Khi + r * APIT + c4, Klo + r * APIT + c4, kv);
            float4 vv = *(const float4*)(stV + idx * 4);
            split_store4(Vhi + r * APIT + c4, Vlo + r * APIT + c4, vv);
        }
        __syncthreads();   // bf16 bufs ready; stage fully consumed

        // prefetch next tile (overlaps with compute below)
        if (kt + 1 < NT) load_kv_async(kt + 1);
        cp_commit();

        float s[8][4];
#pragma unroll
        for (int nt = 0; nt < 8; nt++)
#pragma unroll
            for (int e = 0; e < 4; e++) s[nt][e] = 0.0f;

#pragma unroll
        for (int ks = 0; ks < 8; ks++) {
            uint32_t ah[4], al[4];
            ldsm_x4(ah[0], ah[1], ah[2], ah[3],
                    qhiBase + (ks * 16 + colA) * 2);
            ldsm_x4(al[0], al[1], al[2], al[3],
                    qloBase + (ks * 16 + colA) * 2);
#pragma unroll
            for (int jn = 0; jn < 4; jn++) {
                uint32_t b0, b1, b2, b3;
                ldsm_x4(b0, b1, b2, b3,
                        uKhi + ((jn * 16 + rowK) * APIT + ks * 16 + colK) * 2);
                mma16816(s[2*jn][0], s[2*jn][1], s[2*jn][2], s[2*jn][3],
                         ah[0], ah[1], ah[2], ah[3], b0, b1);
                mma16816(s[2*jn+1][0], s[2*jn+1][1], s[2*jn+1][2], s[2*jn+1][3],
                         ah[0], ah[1], ah[2], ah[3], b2, b3);
                mma16816(s[2*jn][0], s[2*jn][1], s[2*jn][2], s[2*jn][3],
                         al[0], al[1], al[2], al[3], b0, b1);
                mma16816(s[2*jn+1][0], s[2*jn+1][1], s[2*jn+1][2], s[2*jn+1][3],
                         al[0], al[1], al[2], al[3], b2, b3);
                ldsm_x4(b0, b1, b2, b3,
                        uKlo + ((jn * 16 + rowK) * APIT + ks * 16 + colK) * 2);
                mma16816(s[2*jn][0], s[2*jn][1], s[2*jn][2], s[2*jn][3],
                         ah[0], ah[1], ah[2], ah[3], b0, b1);
                mma16816(s[2*jn+1][0], s[2*jn+1][1], s[2*jn+1][2], s[2*jn+1][3],
                         ah[0], ah[1], ah[2], ah[3], b2, b3);
            }
        }

        float tm0 = -1e30f, tm1 = -1e30f;
#pragma unroll
        for (int nt = 0; nt < 8; nt++) {
            s[nt][0] *= sscale; s[nt][1] *= sscale;
            s[nt][2] *= sscale; s[nt][3] *= sscale;
            tm0 = fmaxf(tm0, fmaxf(s[nt][0], s[nt][1]));
            tm1 = fmaxf(tm1, fmaxf(s[nt][2], s[nt][3]));
        }
        tm0 = fmaxf(tm0, __shfl_xor_sync(0xffffffffu, tm0, 1));
        tm0 = fmaxf(tm0, __shfl_xor_sync(0xffffffffu, tm0, 2));
        tm1 = fmaxf(tm1, __shfl_xor_sync(0xffffffffu, tm1, 1));
        tm1 = fmaxf(tm1, __shfl_xor_sync(0xffffffffu, tm1, 2));

        float mn0 = fmaxf(m0, tm0), mn1 = fmaxf(m1, tm1);
        float al0 = __expf(m0 - mn0), al1 = __expf(m1 - mn1);
        m0 = mn0; m1 = mn1;

        float rs0 = 0.0f, rs1 = 0.0f;
        uint32_t aPhi[4][4], aPlo[4][4];
#pragma unroll
        for (int nt = 0; nt < 8; nt++) {
            float p0 = __expf(s[nt][0] - mn0);
            float p1 = __expf(s[nt][1] - mn0);
            float p2 = __expf(s[nt][2] - mn1);
            float p3 = __expf(s[nt][3] - mn1);
            rs0 += p0 + p1; rs1 += p2 + p3;
            __nv_bfloat16 f0 = __float2bfloat16(p0);
            __nv_bfloat16 f1 = __float2bfloat16(p1);
            __nv_bfloat16 f2 = __float2bfloat16(p2);
            __nv_bfloat16 f3 = __float2bfloat16(p3);
            __nv_bfloat16 g0 = __float2bfloat16(p0 - __bfloat162float(f0));
            __nv_bfloat16 g1 = __float2bfloat16(p1 - __bfloat162float(f1));
            __nv_bfloat16 g2 = __float2bfloat16(p2 - __bfloat162float(f2));
            __nv_bfloat16 g3 = __float2bfloat16(p3 - __bfloat162float(f3));
            int t4 = nt >> 1, hh = (nt & 1) << 1;
            aPhi[t4][hh]     = pack_bf16x2(f0, f1);
            aPhi[t4][hh + 1] = pack_bf16x2(f2, f3);
            aPlo[t4][hh]     = pack_bf16x2(g0, g1);
            aPlo[t4][hh + 1] = pack_bf16x2(g2, g3);
        }
        rs0 += __shfl_xor_sync(0xffffffffu, rs0, 1);
        rs0 += __shfl_xor_sync(0xffffffffu, rs0, 2);
        rs1 += __shfl_xor_sync(0xffffffffu, rs1, 1);
        rs1 += __shfl_xor_sync(0xffffffffu, rs1, 2);
        l0 = l0 * al0 + rs0;
        l1 = l1 * al1 + rs1;

#pragma unroll
        for (int nt = 0; nt < 16; nt++) {
            oacc[nt][0] *= al0; oacc[nt][1] *= al0;
            oacc[nt][2] *= al1; oacc[nt][3] *= al1;
        }

#pragma unroll
        for (int k4 = 0; k4 < 4; k4++) {
#pragma unroll
            for (int jd = 0; jd < 8; jd++) {
                uint32_t b0, b1, b2, b3;
                ldsm_x4_t(b0, b1, b2, b3,
                          uVhi + ((k4 * 16 + rowV) * APIT + jd * 16 + colV) * 2);
                mma16816(oacc[2*jd][0], oacc[2*jd][1], oacc[2*jd][2], oacc[2*jd][3],
                         aPhi[k4][0], aPhi[k4][1], aPhi[k4][2], aPhi[k4][3], b0, b1);
                mma16816(oacc[2*jd+1][0], oacc[2*jd+1][1], oacc[2*jd+1][2], oacc[2*jd+1][3],
                         aPhi[k4][0], aPhi[k4][1], aPhi[k4][2], aPhi[k4][3], b2, b3);
                mma16816(oacc[2*jd][0], oacc[2*jd][1], oacc[2*jd][2], oacc[2*jd][3],
                         aPlo[k4][0], aPlo[k4][1], aPlo[k4][2], aPlo[k4][3], b0, b1);
                mma16816(oacc[2*jd+1][0], oacc[2*jd+1][1], oacc[2*jd+1][2], oacc[2*jd+1][3],
                         aPlo[k4][0], aPlo[k4][1], aPlo[k4][2], aPlo[k4][3], b2, b3);
                ldsm_x4_t(b0, b1, b2, b3,
                          uVlo + ((k4 * 16 + rowV) * APIT + jd * 16 + colV) * 2);
                mma16816(oacc[2*jd][0], oacc[2*jd][1], oacc[2*jd][2], oacc[2*jd][3],
                         aPhi[k4][0], aPhi[k4][1], aPhi[k4][2], aPhi[k4][3], b0, b1);
                mma16816(oacc[2*jd+1][0], oacc[2*jd+1][1], oacc[2*jd+1][2], oacc[2*jd+1][3],
                         aPhi[k4][0], aPhi[k4][1], aPhi[k4][2], aPhi[k4][3], b2, b3);
            }
        }
    }

    // ---- normalize + write split [hi|lo|hi] rows of g_a ----
    float inv0 = 1.0f / l0, inv1 = 1.0f / l1;
    int row0 = warp * 16 + (lane >> 2);
    int c0 = (lane & 3) * 2;
#pragma unroll
    for (int nt = 0; nt < 16; nt++) {
        __nv_bfloat16* r0p = Og + (size_t)row0 * KSPLIT;
        __nv_bfloat16* r1p = Og + (size_t)(row0 + 8) * KSPLIT;
        store_split2(r0p, nt * 8 + c0, oacc[nt][0] * inv0, oacc[nt][1] * inv0);
        store_split2(r1p, nt * 8 + c0, oacc[nt][2] * inv1, oacc[nt][3] * inv1);
    }
}

// ============================================================================
// host
// ============================================================================
extern "C" void kernel_launch(void* const* d_in, const int* in_sizes, int n_in,
                              void* d_out, int out_size) {
    const float* x   = (const float*)d_in[0];
    const float* qr  = (const float*)d_in[1];
    const float* kr  = (const float*)d_in[2];
    const float* Wq  = (const float*)d_in[3];
    const float* Wk  = (const float*)d_in[4];
    const float* Wv  = (const float*)d_in[5];
    const float* Wo  = (const float*)d_in[6];
    const float* bo  = (const float*)d_in[7];
    float* out = (float*)d_out;

    void *pq, *pk, *pv, *pab, *pwq, *pwk, *pwv, *pwo;
    cudaGetSymbolAddress(&pq,  g_q);
    cudaGetSymbolAddress(&pk,  g_k);
    cudaGetSymbolAddress(&pv,  g_v);
    cudaGetSymbolAddress(&pab, g_a);
    cudaGetSymbolAddress(&pwq, g_wq);
    cudaGetSymbolAddress(&pwk, g_wk);
    cudaGetSymbolAddress(&pwv, g_wv);
    cudaGetSymbolAddress(&pwo, g_wo);

    cudaFuncSetAttribute(gemm_bf16_kernel,
                         cudaFuncAttributeMaxDynamicSharedMemorySize,
                         GEMM_SMEM_BYTES);
    cudaFuncSetAttribute(gemm_qkv_kernel,
                         cudaFuncAttributeMaxDynamicSharedMemorySize,
                         GEMM_SMEM_BYTES);
    cudaFuncSetAttribute(attn_mma_kernel,
                         cudaFuncAttributeMaxDynamicSharedMemorySize,
                         ATT3_SMEM_BYTES);

    int wElems = DMODEL * DMODEL;
    split_b_kernel<<<(wElems + 255) / 256, 256>>>(Wq, (__nv_bfloat16*)pwq);
    split_b_kernel<<<(wElems + 255) / 256, 256>>>(Wk, (__nv_bfloat16*)pwk);
    split_b_kernel<<<(wElems + 255) / 256, 256>>>(Wv, (__nv_bfloat16*)pwv);
    split_b_kernel<<<(wElems + 255) / 256, 256>>>(Wo, (__nv_bfloat16*)pwo);

    int aElems = ROWS * DMODEL;
    split_a_kernel<<<(aElems + 255) / 256, 256>>>(x, (__nv_bfloat16*)pab);

    dim3 qkv_grid(DMODEL / GBN, ROWS / GBM, 3);   // (16, 32, 3)
    gemm_qkv_kernel<<<qkv_grid, 256, GEMM_SMEM_BYTES>>>(
        (const __nv_bfloat16*)pab,
        (const __nv_bfloat16*)pwq, (const __nv_bfloat16*)pwk,
        (const __nv_bfloat16*)pwv,
        (float*)pq, (float*)pk, (float*)pv,
        ROWS, DMODEL, KSPLIT);

    int rope_pairs = BATCH * SEQ * HEADS * (DH / 2);
    rope_kernel<<<rope_pairs / 256, 256>>>((float*)pq, qr, 0.08838834764831845f);
    rope_kernel<<<rope_pairs / 256, 256>>>((float*)pk, kr, 1.0f);

    attn_mma_kernel<<<dim3(SEQ / AQT, BATCH * HEADS), 256, ATT3_SMEM_BYTES>>>(
        (const float*)pq, (const float*)pk, (const float*)pv,
        (__nv_bfloat16*)pab);

    gemm_bf16_kernel<<<dim3(DMODEL / GBN, ROWS / GBM), 256, GEMM_SMEM_BYTES>>>(
        (const __nv_bfloat16*)pab, (const __nv_bfloat16*)pwo, out,
        ROWS, DMODEL, KSPLIT, bo);
}

// round 14
// speedup vs baseline: 1.0087x; 1.0087x over previous
#include <cuda_runtime.h>
#include <cuda_bf16.h>
#include <cstdint>

// ============================================================================
// AttentionWithRoPE — round 14: revert neutral K/V staging (round-12 attention
// core), fuse 4x split_b into one launch, fuse RoPE into attention Q/K loads.
//   B=2, N=2048, D=2048, H=16, Dh=128
// ============================================================================

#define BATCH   2
#define SEQ     2048
#define DMODEL  2048
#define HEADS   16
#define DH      128
#define ROWS    (BATCH * SEQ)          // 4096
#define KSPLIT  (3 * DMODEL)           // 6144

// ---- scratch (static __device__, no allocations; 16B-aligned) ----
__device__ __align__(16) float g_q[ROWS * DMODEL];
__device__ __align__(16) float g_k[ROWS * DMODEL];
__device__ __align__(16) float g_v[ROWS * DMODEL];
__device__ __align__(16) __nv_bfloat16 g_a  [ROWS * KSPLIT];
__device__ __align__(16) __nv_bfloat16 g_wq [KSPLIT * DMODEL];
__device__ __align__(16) __nv_bfloat16 g_wk [KSPLIT * DMODEL];
__device__ __align__(16) __nv_bfloat16 g_wv [KSPLIT * DMODEL];
__device__ __align__(16) __nv_bfloat16 g_wo [KSPLIT * DMODEL];

// ============================================================================
// common MMA / ldmatrix helpers
// ============================================================================
__device__ __forceinline__ void cp16(uint32_t smem_addr, const void* gptr) {
    asm volatile("cp.async.cg.shared.global [%0], [%1], 16;"
                 :: "r"(smem_addr), "l"(gptr));
}
__device__ __forceinline__ void cp_commit() {
    asm volatile("cp.async.commit_group;");
}
template <int Nwait>
__device__ __forceinline__ void cp_wait() {
    asm volatile("cp.async.wait_group %0;" :: "n"(Nwait));
}
__device__ __forceinline__ void ldsm_x4(uint32_t& r0, uint32_t& r1,
                                        uint32_t& r2, uint32_t& r3,
                                        uint32_t addr) {
    asm volatile("ldmatrix.sync.aligned.m8n8.x4.shared.b16 {%0,%1,%2,%3}, [%4];"
                 : "=r"(r0), "=r"(r1), "=r"(r2), "=r"(r3) : "r"(addr));
}
__device__ __forceinline__ void ldsm_x4_t(uint32_t& r0, uint32_t& r1,
                                          uint32_t& r2, uint32_t& r3,
                                          uint32_t addr) {
    asm volatile("ldmatrix.sync.aligned.m8n8.x4.trans.shared.b16 {%0,%1,%2,%3}, [%4];"
                 : "=r"(r0), "=r"(r1), "=r"(r2), "=r"(r3) : "r"(addr));
}
__device__ __forceinline__ void mma16816(float& c0, float& c1, float& c2, float& c3,
                                         uint32_t a0, uint32_t a1, uint32_t a2,
                                         uint32_t a3, uint32_t b0, uint32_t b1) {
    asm volatile(
        "mma.sync.aligned.m16n8k16.row.col.f32.bf16.bf16.f32 "
        "{%0,%1,%2,%3}, {%4,%5,%6,%7}, {%8,%9}, {%0,%1,%2,%3};"
        : "+f"(c0), "+f"(c1), "+f"(c2), "+f"(c3)
        : "r"(a0), "r"(a1), "r"(a2), "r"(a3), "r"(b0), "r"(b1));
}
__device__ __forceinline__ uint32_t pack_bf16x2(__nv_bfloat16 lo, __nv_bfloat16 hi) {
    __nv_bfloat162 p = __halves2bfloat162(lo, hi);
    return *reinterpret_cast<uint32_t*>(&p);
}

// ============================================================================
// hi/lo split kernels — SCALAR (verified). split_b fused over 4 weights.
// ============================================================================
__global__ __launch_bounds__(256)
void split_a_kernel(const float* __restrict__ X, __nv_bfloat16* __restrict__ A) {
    int i = blockIdx.x * blockDim.x + threadIdx.x;
    if (i >= ROWS * DMODEL) return;
    int r = i / DMODEL, c = i % DMODEL;
    float x = X[i];
    __nv_bfloat16 hi = __float2bfloat16(x);
    __nv_bfloat16 lo = __float2bfloat16(x - __bfloat162float(hi));
    __nv_bfloat16* row = A + (size_t)r * KSPLIT;
    row[c]              = hi;
    row[DMODEL + c]     = lo;
    row[2 * DMODEL + c] = hi;
}
__global__ __launch_bounds__(256)
void split_b4_kernel(const float* __restrict__ W0, const float* __restrict__ W1,
                     const float* __restrict__ W2, const float* __restrict__ W3,
                     __nv_bfloat16* __restrict__ B0, __nv_bfloat16* __restrict__ B1,
                     __nv_bfloat16* __restrict__ B2, __nv_bfloat16* __restrict__ B3) {
    const float* W = (blockIdx.y == 0) ? W0 : (blockIdx.y == 1) ? W1
                   : (blockIdx.y == 2) ? W2 : W3;
    __nv_bfloat16* Bo = (blockIdx.y == 0) ? B0 : (blockIdx.y == 1) ? B1
                      : (blockIdx.y == 2) ? B2 : B3;
    int i = blockIdx.x * blockDim.x + threadIdx.x;
    if (i >= DMODEL * DMODEL) return;
    float w = W[i];
    __nv_bfloat16 hi = __float2bfloat16(w);
    __nv_bfloat16 lo = __float2bfloat16(w - __bfloat162float(hi));
    Bo[i]                                 = hi;
    Bo[(size_t)DMODEL * DMODEL + i]       = hi;
    Bo[(size_t)2 * DMODEL * DMODEL + i]   = lo;
}

// ============================================================================
// bf16 tensor-core GEMM body: BM=BN=128, BK=64, 3-stage single-sync (verified)
// ============================================================================
#define GBM 128
#define GBN 128
#define GBK 64
#define GSTAGES 3
#define APITCH 72
#define BPITCH 136
#define A_STAGE_ELEMS (GBM * APITCH)
#define B_STAGE_ELEMS (GBK * BPITCH)
#define GEMM_SMEM_BYTES (GSTAGES * (A_STAGE_ELEMS + B_STAGE_ELEMS) * 2)  // 107520

__device__ __forceinline__ void gemm_body(const __nv_bfloat16* __restrict__ A,
                                          const __nv_bfloat16* __restrict__ B,
                                          float* __restrict__ C,
                                          int M, int N, int K,
                                          const float* __restrict__ bias) {
    extern __shared__ __nv_bfloat16 sm[];
    __nv_bfloat16* sA = sm;
    __nv_bfloat16* sB = sm + GSTAGES * A_STAGE_ELEMS;

    const int tid  = threadIdx.x;
    const int warp = tid >> 5;
    const int lane = tid & 31;
    const int wm = warp >> 2;
    const int wn = warp & 3;
    const int bx = blockIdx.x;
    const int by = blockIdx.y;

    const int at_row   = tid >> 3;
    const int at_chunk = (tid & 7) << 3;
    const int bt_row   = tid >> 4;
    const int bt_chunk = (tid & 15) << 3;

    const __nv_bfloat16* Ag = A + (size_t)(by * GBM + at_row) * K + at_chunk;
    const __nv_bfloat16* Bg = B + (size_t)bt_row * N + bx * GBN + bt_chunk;

    uint32_t sA_u32 = (uint32_t)__cvta_generic_to_shared(sA);
    uint32_t sB_u32 = (uint32_t)__cvta_generic_to_shared(sB);

    auto load_tile = [&](int stage, int k0) {
        uint32_t a_dst = sA_u32 + (stage * A_STAGE_ELEMS + at_row * APITCH + at_chunk) * 2;
#pragma unroll
        for (int b = 0; b < 4; b++)
            cp16(a_dst + b * 32 * APITCH * 2, Ag + (size_t)(32 * b) * K + k0);
        uint32_t b_dst = sB_u32 + (stage * B_STAGE_ELEMS + bt_row * BPITCH + bt_chunk) * 2;
#pragma unroll
        for (int b = 0; b < 4; b++)
            cp16(b_dst + b * 16 * BPITCH * 2, Bg + (size_t)(k0 + 16 * b) * N);
    };

    float acc[4][4][4];
#pragma unroll
    for (int i = 0; i < 4; i++)
#pragma unroll
        for (int j = 0; j < 4; j++)
#pragma unroll
            for (int r = 0; r < 4; r++) acc[i][j][r] = 0.0f;

    const int KT = K / GBK;   // 96

    load_tile(0, 0);        cp_commit();
    load_tile(1, GBK);      cp_commit();

    const int a_lrow = (lane & 15);
    const int a_lcol = (lane >> 4) << 3;

    int st = 0, wst = 2;
    for (int kt = 0; kt < KT; kt++) {
        cp_wait<1>();
        __syncthreads();

        if (kt + 2 < KT) load_tile(wst, (kt + 2) * GBK);
        cp_commit();

        uint32_t aBase = sA_u32 + (st * A_STAGE_ELEMS) * 2;
        uint32_t bBase = sB_u32 + (st * B_STAGE_ELEMS) * 2;

#pragma unroll
        for (int ks = 0; ks < 4; ks++) {
            uint32_t a[4][4];
#pragma unroll
            for (int i = 0; i < 4; i++) {
                int row = wm * 64 + i * 16 + a_lrow;
                int col = ks * 16 + a_lcol;
                ldsm_x4(a[i][0], a[i][1], a[i][2], a[i][3],
                        aBase + (row * APITCH + col) * 2);
            }
            uint32_t b[4][2];
#pragma unroll
            for (int j2 = 0; j2 < 2; j2++) {
                int row = ks * 16 + a_lrow;
                int col = wn * 32 + j2 * 16 + a_lcol;
                uint32_t r0, r1, r2, r3;
                ldsm_x4_t(r0, r1, r2, r3, bBase + (row * BPITCH + col) * 2);
                b[2 * j2][0] = r0; b[2 * j2][1] = r1;
                b[2 * j2 + 1][0] = r2; b[2 * j2 + 1][1] = r3;
            }
#pragma unroll
            for (int i = 0; i < 4; i++)
#pragma unroll
                for (int j = 0; j < 4; j++)
                    mma16816(acc[i][j][0], acc[i][j][1], acc[i][j][2], acc[i][j][3],
                             a[i][0], a[i][1], a[i][2], a[i][3],
                             b[j][0], b[j][1]);
        }

        if (++st == GSTAGES) st = 0;
        if (++wst == GSTAGES) wst = 0;
    }

    const int row_base = by * GBM + wm * 64 + (lane >> 2);
    const int col_base = bx * GBN + wn * 32 + (lane & 3) * 2;
#pragma unroll
    for (int i = 0; i < 4; i++) {
#pragma unroll
        for (int j = 0; j < 4; j++) {
            int c = col_base + j * 8;
            float b0 = bias ? bias[c]     : 0.0f;
            float b1 = bias ? bias[c + 1] : 0.0f;
            float* p0 = C + (size_t)(row_base + i * 16) * N + c;
            float* p1 = C + (size_t)(row_base + i * 16 + 8) * N + c;
            p0[0] = acc[i][j][0] + b0; p0[1] = acc[i][j][1] + b1;
            p1[0] = acc[i][j][2] + b0; p1[1] = acc[i][j][3] + b1;
        }
    }
}

__global__ __launch_bounds__(256, 2)
void gemm_bf16_kernel(const __nv_bfloat16* __restrict__ A,
                      const __nv_bfloat16* __restrict__ B,
                      float* __restrict__ C, int M, int N, int K,
                      const float* __restrict__ bias) {
    gemm_body(A, B, C, M, N, K, bias);
}

__global__ __launch_bounds__(256, 2)
void gemm_qkv_kernel(const __nv_bfloat16* __restrict__ A,
                     const __nv_bfloat16* __restrict__ Bq,
                     const __nv_bfloat16* __restrict__ Bk,
                     const __nv_bfloat16* __restrict__ Bv,
                     float* __restrict__ Cq,
                     float* __restrict__ Ck,
                     float* __restrict__ Cv,
                     int M, int N, int K) {
    const __nv_bfloat16* B = (blockIdx.z == 0) ? Bq : (blockIdx.z == 1) ? Bk : Bv;
    float*               C = (blockIdx.z == 0) ? Cq : (blockIdx.z == 1) ? Ck : Cv;
    gemm_body(A, B, C, M, N, K, nullptr);
}

// ============================================================================
// MMA flash attention, hi/lo split, RoPE fused into Q/K tile loads.
// ============================================================================
#define AQT   128
#define AKT   64
#define APIT  136
#define AQ_ELEMS  (AQT * APIT)
#define AKV_ELEMS (AKT * APIT)
#define ATT2_SMEM_BYTES ((2 * AQ_ELEMS + 4 * AKV_ELEMS) * 2)   // 139264

__device__ __forceinline__ void split_store4(__nv_bfloat16* hiP,
                                             __nv_bfloat16* loP, float4 v) {
    __nv_bfloat16 h0 = __float2bfloat16(v.x);
    __nv_bfloat16 h1 = __float2bfloat16(v.y);
    __nv_bfloat16 h2 = __float2bfloat16(v.z);
    __nv_bfloat16 h3 = __float2bfloat16(v.w);
    __nv_bfloat16 l0 = __float2bfloat16(v.x - __bfloat162float(h0));
    __nv_bfloat16 l1 = __float2bfloat16(v.y - __bfloat162float(h1));
    __nv_bfloat16 l2 = __float2bfloat16(v.z - __bfloat162float(h2));
    __nv_bfloat16 l3 = __float2bfloat16(v.w - __bfloat162float(h3));
    *(__nv_bfloat162*)(hiP)     = __halves2bfloat162(h0, h1);
    *(__nv_bfloat162*)(hiP + 2) = __halves2bfloat162(h2, h3);
    *(__nv_bfloat162*)(loP)     = __halves2bfloat162(l0, l1);
    *(__nv_bfloat162*)(loP + 2) = __halves2bfloat162(l2, l3);
}

// apply rope to a float4 covering two complete (re,im) pairs
__device__ __forceinline__ float4 rope4(float4 v, float4 rp, float scale) {
    float4 o;
    float xr0 = v.x * scale, xi0 = v.y * scale;
    float xr1 = v.z * scale, xi1 = v.w * scale;
    o.x = xr0 * rp.x - xi0 * rp.y;
    o.y = xr0 * rp.y + xi0 * rp.x;
    o.z = xr1 * rp.z - xi1 * rp.w;
    o.w = xr1 * rp.w + xi1 * rp.z;
    return o;
}

__device__ __forceinline__ void store_split2(__nv_bfloat16* row, int c,
                                             float v0, float v1) {
    __nv_bfloat16 h0 = __float2bfloat16(v0);
    __nv_bfloat16 h1 = __float2bfloat16(v1);
    __nv_bfloat16 l0 = __float2bfloat16(v0 - __bfloat162float(h0));
    __nv_bfloat16 l1 = __float2bfloat16(v1 - __bfloat162float(h1));
    __nv_bfloat162 hp = __halves2bfloat162(h0, h1);
    *(__nv_bfloat162*)(row + c)              = hp;
    *(__nv_bfloat162*)(row + DMODEL + c)     = __halves2bfloat162(l0, l1);
    *(__nv_bfloat162*)(row + 2 * DMODEL + c) = hp;
}

__global__ __launch_bounds__(256, 1)
void attn_mma_kernel(const float* __restrict__ Q, const float* __restrict__ K,
                     const float* __restrict__ V,
                     const float* __restrict__ ropeQ,
                     const float* __restrict__ ropeK,
                     __nv_bfloat16* __restrict__ Oa) {
    extern __shared__ __nv_bfloat16 smb[];
    __nv_bfloat16* Qhi = smb;
    __nv_bfloat16* Qlo = smb + AQ_ELEMS;
    __nv_bfloat16* Khi = smb + 2 * AQ_ELEMS;
    __nv_bfloat16* Klo = Khi + AKV_ELEMS;
    __nv_bfloat16* Vhi = Klo + AKV_ELEMS;
    __nv_bfloat16* Vlo = Vhi + AKV_ELEMS;

    const int tid  = threadIdx.x;
    const int warp = tid >> 5;
    const int lane = tid & 31;
    const int qt = blockIdx.x;
    const int bh = blockIdx.y;
    const int b  = bh >> 4;
    const int h  = bh & 15;

    const float* Qg = Q + ((size_t)b * SEQ + qt * AQT) * DMODEL + h * DH;
    const float* Kg = K + ((size_t)b * SEQ) * DMODEL + h * DH;
    const float* Vg = V + ((size_t)b * SEQ) * DMODEL + h * DH;
    const float* rQ = ropeQ + ((size_t)b * SEQ + qt * AQT) * DH;
    const float* rK = ropeK + ((size_t)b * SEQ) * DH;
    __nv_bfloat16* Og = Oa + ((size_t)b * SEQ + qt * AQT) * KSPLIT + h * DH;

    const float qscale = 0.08838834764831845f;  // Dh^-0.5 applied pre-rope

    // ---- load + rope + split Q (128x128) ----
#pragma unroll
    for (int it = 0; it < 16; it++) {
        int idx = tid + it * 256;
        int r = idx >> 5, c4 = (idx & 31) << 2;
        float4 v  = *(const float4*)(Qg + (size_t)r * DMODEL + c4);
        float4 rp = *(const float4*)(rQ + (size_t)r * DH + c4);
        float4 o  = rope4(v, rp, qscale);
        split_store4(Qhi + r * APIT + c4, Qlo + r * APIT + c4, o);
    }

    uint32_t uQhi = (uint32_t)__cvta_generic_to_shared(Qhi);
    uint32_t uQlo = (uint32_t)__cvta_generic_to_shared(Qlo);
    uint32_t uKhi = (uint32_t)__cvta_generic_to_shared(Khi);
    uint32_t uKlo = (uint32_t)__cvta_generic_to_shared(Klo);
    uint32_t uVhi = (uint32_t)__cvta_generic_to_shared(Vhi);
    uint32_t uVlo = (uint32_t)__cvta_generic_to_shared(Vlo);

    const float sscale = 0.08838834764831845f;  // 1/sqrt(128) on scores

    float m0 = -1e30f, m1 = -1e30f, l0 = 0.0f, l1 = 0.0f;
    float oacc[16][4];
#pragma unroll
    for (int nt = 0; nt < 16; nt++)
#pragma unroll
        for (int e = 0; e < 4; e++) oacc[nt][e] = 0.0f;

    const int rowA = lane & 15;
    const int colA = (lane >> 4) << 3;
    const int rowK = (lane & 7) + ((lane >> 4) << 3);
    const int colK = ((lane >> 3) & 1) << 3;
    const int rowV = lane & 15;
    const int colV = (lane >> 4) << 3;

    const uint32_t qhiBase = uQhi + ((warp * 16 + rowA) * APIT) * 2;
    const uint32_t qloBase = uQlo + ((warp * 16 + rowA) * APIT) * 2;

    for (int kt = 0; kt < SEQ / AKT; kt++) {
        __syncthreads();
        // ---- load + rope(K) + split K; load + split V ----
#pragma unroll
        for (int it = 0; it < 8; it++) {
            int idx = tid + it * 256;
            int r = idx >> 5, c4 = (idx & 31) << 2;
            float4 kv = *(const float4*)(Kg + (size_t)(kt * AKT + r) * DMODEL + c4);
            float4 rp = *(const float4*)(rK + (size_t)(kt * AKT + r) * DH + c4);
            float4 ko = rope4(kv, rp, 1.0f);
            split_store4(Khi + r * APIT + c4, Klo + r * APIT + c4, ko);
            float4 vv = *(const float4*)(Vg + (size_t)(kt * AKT + r) * DMODEL + c4);
            split_store4(Vhi + r * APIT + c4, Vlo + r * APIT + c4, vv);
        }
        __syncthreads();

        float s[8][4];
#pragma unroll
        for (int nt = 0; nt < 8; nt++)
#pragma unroll
            for (int e = 0; e < 4; e++) s[nt][e] = 0.0f;

#pragma unroll
        for (int ks = 0; ks < 8; ks++) {
            uint32_t ah[4], al[4];
            ldsm_x4(ah[0], ah[1], ah[2], ah[3],
                    qhiBase + (ks * 16 + colA) * 2);
            ldsm_x4(al[0], al[1], al[2], al[3],
                    qloBase + (ks * 16 + colA) * 2);
#pragma unroll
            for (int jn = 0; jn < 4; jn++) {
                uint32_t b0, b1, b2, b3;
                ldsm_x4(b0, b1, b2, b3,
                        uKhi + ((jn * 16 + rowK) * APIT + ks * 16 + colK) * 2);
                mma16816(s[2*jn][0], s[2*jn][1], s[2*jn][2], s[2*jn][3],
                         ah[0], ah[1], ah[2], ah[3], b0, b1);
                mma16816(s[2*jn+1][0], s[2*jn+1][1], s[2*jn+1][2], s[2*jn+1][3],
                         ah[0], ah[1], ah[2], ah[3], b2, b3);
                mma16816(s[2*jn][0], s[2*jn][1], s[2*jn][2], s[2*jn][3],
                         al[0], al[1], al[2], al[3], b0, b1);
                mma16816(s[2*jn+1][0], s[2*jn+1][1], s[2*jn+1][2], s[2*jn+1][3],
                         al[0], al[1], al[2], al[3], b2, b3);
                ldsm_x4(b0, b1, b2, b3,
                        uKlo + ((jn * 16 + rowK) * APIT + ks * 16 + colK) * 2);
                mma16816(s[2*jn][0], s[2*jn][1], s[2*jn][2], s[2*jn][3],
                         ah[0], ah[1], ah[2], ah[3], b0, b1);
                mma16816(s[2*jn+1][0], s[2*jn+1][1], s[2*jn+1][2], s[2*jn+1][3],
                         ah[0], ah[1], ah[2], ah[3], b2, b3);
            }
        }

        float tm0 = -1e30f, tm1 = -1e30f;
#pragma unroll
        for (int nt = 0; nt < 8; nt++) {
            s[nt][0] *= sscale; s[nt][1] *= sscale;
            s[nt][2] *= sscale; s[nt][3] *= sscale;
            tm0 = fmaxf(tm0, fmaxf(s[nt][0], s[nt][1]));
            tm1 = fmaxf(tm1, fmaxf(s[nt][2], s[nt][3]));
        }
        tm0 = fmaxf(tm0, __shfl_xor_sync(0xffffffffu, tm0, 1));
        tm0 = fmaxf(tm0, __shfl_xor_sync(0xffffffffu, tm0, 2));
        tm1 = fmaxf(tm1, __shfl_xor_sync(0xffffffffu, tm1, 1));
        tm1 = fmaxf(tm1, __shfl_xor_sync(0xffffffffu, tm1, 2));

        float mn0 = fmaxf(m0, tm0), mn1 = fmaxf(m1, tm1);
        float al0 = __expf(m0 - mn0), al1 = __expf(m1 - mn1);
        m0 = mn0; m1 = mn1;

        float rs0 = 0.0f, rs1 = 0.0f;
        uint32_t aPhi[4][4], aPlo[4][4];
#pragma unroll
        for (int nt = 0; nt < 8; nt++) {
            float p0 = __expf(s[nt][0] - mn0);
            float p1 = __expf(s[nt][1] - mn0);
            float p2 = __expf(s[nt][2] - mn1);
            float p3 = __expf(s[nt][3] - mn1);
            rs0 += p0 + p1; rs1 += p2 + p3;
            __nv_bfloat16 f0 = __float2bfloat16(p0);
            __nv_bfloat16 f1 = __float2bfloat16(p1);
            __nv_bfloat16 f2 = __float2bfloat16(p2);
            __nv_bfloat16 f3 = __float2bfloat16(p3);
            __nv_bfloat16 g0 = __float2bfloat16(p0 - __bfloat162float(f0));
            __nv_bfloat16 g1 = __float2bfloat16(p1 - __bfloat162float(f1));
            __nv_bfloat16 g2 = __float2bfloat16(p2 - __bfloat162float(f2));
            __nv_bfloat16 g3 = __float2bfloat16(p3 - __bfloat162float(f3));
            int t4 = nt >> 1, hh = (nt & 1) << 1;
            aPhi[t4][hh]     = pack_bf16x2(f0, f1);
            aPhi[t4][hh + 1] = pack_bf16x2(f2, f3);
            aPlo[t4][hh]     = pack_bf16x2(g0, g1);
            aPlo[t4][hh + 1] = pack_bf16x2(g2, g3);
        }
        rs0 += __shfl_xor_sync(0xffffffffu, rs0, 1);
        rs0 += __shfl_xor_sync(0xffffffffu, rs0, 2);
        rs1 += __shfl_xor_sync(0xffffffffu, rs1, 1);
        rs1 += __shfl_xor_sync(0xffffffffu, rs1, 2);
        l0 = l0 * al0 + rs0;
        l1 = l1 * al1 + rs1;

#pragma unroll
        for (int nt = 0; nt < 16; nt++) {
            oacc[nt][0] *= al0; oacc[nt][1] *= al0;
            oacc[nt][2] *= al1; oacc[nt][3] *= al1;
        }

#pragma unroll
        for (int k4 = 0; k4 < 4; k4++) {
#pragma unroll
            for (int jd = 0; jd < 8; jd++) {
                uint32_t b0, b1, b2, b3;
                ldsm_x4_t(b0, b1, b2, b3,
                          uVhi + ((k4 * 16 + rowV) * APIT + jd * 16 + colV) * 2);
                mma16816(oacc[2*jd][0], oacc[2*jd][1], oacc[2*jd][2], oacc[2*jd][3],
                         aPhi[k4][0], aPhi[k4][1], aPhi[k4][2], aPhi[k4][3], b0, b1);
                mma16816(oacc[2*jd+1][0], oacc[2*jd+1][1], oacc[2*jd+1][2], oacc[2*jd+1][3],
                         aPhi[k4][0], aPhi[k4][1], aPhi[k4][2], aPhi[k4][3], b2, b3);
                mma16816(oacc[2*jd][0], oacc[2*jd][1], oacc[2*jd][2], oacc[2*jd][3],
                         aPlo[k4][0], aPlo[k4][1], aPlo[k4][2], aPlo[k4][3], b0, b1);
                mma16816(oacc[2*jd+1][0], oacc[2*jd+1][1], oacc[2*jd+1][2], oacc[2*jd+1][3],
                         aPlo[k4][0], aPlo[k4][1], aPlo[k4][2], aPlo[k4][3], b2, b3);
                ldsm_x4_t(b0, b1, b2, b3,
                          uVlo + ((k4 * 16 + rowV) * APIT + jd * 16 + colV) * 2);
                mma16816(oacc[2*jd][0], oacc[2*jd][1], oacc[2*jd][2], oacc[2*jd][3],
                         aPhi[k4][0], aPhi[k4][1], aPhi[k4][2], aPhi[k4][3], b0, b1);
                mma16816(oacc[2*jd+1][0], oacc[2*jd+1][1], oacc[2*jd+1][2], oacc[2*jd+1][3],
                         aPhi[k4][0], aPhi[k4][1], aPhi[k4][2], aPhi[k4][3], b2, b3);
            }
        }
    }

    // ---- normalize + write split [hi|lo|hi] rows of g_a ----
    float inv0 = 1.0f / l0, inv1 = 1.0f / l1;
    int row0 = warp * 16 + (lane >> 2);
    int c0 = (lane & 3) * 2;
#pragma unroll
    for (int nt = 0; nt < 16; nt++) {
        __nv_bfloat16* r0p = Og + (size_t)row0 * KSPLIT;
        __nv_bfloat16* r1p = Og + (size_t)(row0 + 8) * KSPLIT;
        store_split2(r0p, nt * 8 + c0, oacc[nt][0] * inv0, oacc[nt][1] * inv0);
        store_split2(r1p, nt * 8 + c0, oacc[nt][2] * inv1, oacc[nt][3] * inv1);
    }
}

// ============================================================================
// host
// ============================================================================
extern "C" void kernel_launch(void* const* d_in, const int* in_sizes, int n_in,
                              void* d_out, int out_size) {
    const float* x   = (const float*)d_in[0];
    const float* qr  = (const float*)d_in[1];
    const float* kr  = (const float*)d_in[2];
    const float* Wq  = (const float*)d_in[3];
    const float* Wk  = (const float*)d_in[4];
    const float* Wv  = (const float*)d_in[5];
    const float* Wo  = (const float*)d_in[6];
    const float* bo  = (const float*)d_in[7];
    float* out = (float*)d_out;

    void *pq, *pk, *pv, *pab, *pwq, *pwk, *pwv, *pwo;
    cudaGetSymbolAddress(&pq,  g_q);
    cudaGetSymbolAddress(&pk,  g_k);
    cudaGetSymbolAddress(&pv,  g_v);
    cudaGetSymbolAddress(&pab, g_a);
    cudaGetSymbolAddress(&pwq, g_wq);
    cudaGetSymbolAddress(&pwk, g_wk);
    cudaGetSymbolAddress(&pwv, g_wv);
    cudaGetSymbolAddress(&pwo, g_wo);

    cudaFuncSetAttribute(gemm_bf16_kernel,
                         cudaFuncAttributeMaxDynamicSharedMemorySize,
                         GEMM_SMEM_BYTES);
    cudaFuncSetAttribute(gemm_qkv_kernel,
                         cudaFuncAttributeMaxDynamicSharedMemorySize,
                         GEMM_SMEM_BYTES);
    cudaFuncSetAttribute(attn_mma_kernel,
                         cudaFuncAttributeMaxDynamicSharedMemorySize,
                         ATT2_SMEM_BYTES);

    int wElems = DMODEL * DMODEL;
    split_b4_kernel<<<dim3((wElems + 255) / 256, 4), 256>>>(
        Wq, Wk, Wv, Wo,
        (__nv_bfloat16*)pwq, (__nv_bfloat16*)pwk,
        (__nv_bfloat16*)pwv, (__nv_bfloat16*)pwo);

    int aElems = ROWS * DMODEL;
    split_a_kernel<<<(aElems + 255) / 256, 256>>>(x, (__nv_bfloat16*)pab);

    dim3 qkv_grid(DMODEL / GBN, ROWS / GBM, 3);   // (16, 32, 3)
    gemm_qkv_kernel<<<qkv_grid, 256, GEMM_SMEM_BYTES>>>(
        (const __nv_bfloat16*)pab,
        (const __nv_bfloat16*)pwq, (const __nv_bfloat16*)pwk,
        (const __nv_bfloat16*)pwv,
        (float*)pq, (float*)pk, (float*)pv,
        ROWS, DMODEL, KSPLIT);

    // rope fused into attention Q/K loads — no separate rope kernels
    attn_mma_kernel<<<dim3(SEQ / AQT, BATCH * HEADS), 256, ATT2_SMEM_BYTES>>>(
        (const float*)pq, (const float*)pk, (const float*)pv,
        qr, kr, (__nv_bfloat16*)pab);

    gemm_bf16_kernel<<<dim3(DMODEL / GBN, ROWS / GBM), 256, GEMM_SMEM_BYTES>>>(
        (const __nv_bfloat16*)pab, (const __nv_bfloat16*)pwo, out,
        ROWS, DMODEL, KSPLIT, bo);
}